// round 16
// baseline (speedup 1.0000x reference)
#include <cuda_runtime.h>
#include <cuda_fp16.h>
#include <cuda_bf16.h>
#include <cstdint>

// self_attention_9225589752302 — round 15: BK=32 (2048 CTAs) to kill wave quantization.
// 8 warps = 2 m-strips(16) x 4 j-quarters(16). GEMM1 fp16 3-pass (log2), GEMM2 fp16 1-pass.
// Elementwise prep, ldmatrix.trans K frags, 3-stage cp.async, 2 CTAs/SM.

#define NTHREADS 256
#define LOG2E 1.4426950408889634f

// ---- global scratch (elementwise layouts) ----
__device__ __half g_KHi[4194304];   // [pb][c=64][k=1024], pre-scaled by log2e
__device__ __half g_KLo[4194304];
__device__ __half g_JHi[4194304];   // [pb][c=64][j=1024]
__device__ __half g_JLo[4194304];
__device__ __half g_VH [4194304];   // [pb][c=64][j=1024] single fp16

// ---- smem: K 16KB | 3 stages x 24KB | LRED ----
#define KHIo 0u            // K [c=64 rows][128B row, first 64B = 32 k], swz ((c&7)<<4)
#define KLOo 8192u
#define STG  16384u
#define SSZ  24576u
#define JHIo 0u
#define JLOo 8192u
#define VHo  16384u
#define LRED (16384u + 3u * 24576u)     // 90112
#define SMEM_BYTES (LRED + 1536u)
#define OSTAGE 0u                       // epilogue f32 [64 c][32 k] = 8KB over K region

static __device__ __forceinline__ uint32_t smem_u32(const void* p) {
    uint32_t a;
    asm("{ .reg .u64 t; cvta.to.shared.u64 t, %1; cvt.u32.u64 %0, t; }" : "=r"(a) : "l"(p));
    return a;
}
static __device__ __forceinline__ float ex2f(float x) {
    float r;
    asm("ex2.approx.ftz.f32 %0, %1;" : "=f"(r) : "f"(x));
    return r;
}
static __device__ __forceinline__ void cpa16(uint32_t dst, const void* src) {
    asm volatile("cp.async.cg.shared.global [%0], [%1], 16;" :: "r"(dst), "l"(src));
}
#define CP_COMMIT() asm volatile("cp.async.commit_group;" ::: "memory")
#define CP_WAIT1()  asm volatile("cp.async.wait_group 1;" ::: "memory")
#define CP_WAIT0()  asm volatile("cp.async.wait_group 0;" ::: "memory")

static __device__ __forceinline__ void ldsm4t(uint32_t r[4], uint32_t a) {
    asm volatile("ldmatrix.sync.aligned.m8n8.x4.trans.shared.b16 {%0,%1,%2,%3}, [%4];"
        : "=r"(r[0]), "=r"(r[1]), "=r"(r[2]), "=r"(r[3]) : "r"(a));
}
static __device__ __forceinline__ void ldsm4(uint32_t r[4], uint32_t a) {
    asm volatile("ldmatrix.sync.aligned.m8n8.x4.shared.b16 {%0,%1,%2,%3}, [%4];"
        : "=r"(r[0]), "=r"(r[1]), "=r"(r[2]), "=r"(r[3]) : "r"(a));
}
static __device__ __forceinline__ void mma_f16(float d[4], const uint32_t a[4], uint32_t b0, uint32_t b1) {
    asm("mma.sync.aligned.m16n8k16.row.col.f32.f16.f16.f32 "
        "{%0,%1,%2,%3}, {%4,%5,%6,%7}, {%8,%9}, {%0,%1,%2,%3};"
        : "+f"(d[0]), "+f"(d[1]), "+f"(d[2]), "+f"(d[3])
        : "r"(a[0]), "r"(a[1]), "r"(a[2]), "r"(a[3]), "r"(b0), "r"(b1));
}
static __device__ __forceinline__ uint32_t u32h2(__half2 h) { return *(uint32_t*)&h; }

// ---- prep: pure elementwise (unchanged from R14) ----
__global__ __launch_bounds__(256)
void prep_kernel(const float4* __restrict__ K4, const float4* __restrict__ J4,
                 const float4* __restrict__ V4) {
    unsigned b = blockIdx.x * 256u + threadIdx.x;
    unsigned f = b * 2u;
    float4 ja = J4[f], jb = J4[f + 1];
    __half2 jh0 = __floats2half2_rn(ja.x, ja.y), jh1 = __floats2half2_rn(ja.z, ja.w);
    __half2 jh2 = __floats2half2_rn(jb.x, jb.y), jh3 = __floats2half2_rn(jb.z, jb.w);
    float2 a0 = __half22float2(jh0), a1 = __half22float2(jh1);
    float2 a2 = __half22float2(jh2), a3 = __half22float2(jh3);
    __half2 jl0 = __floats2half2_rn(ja.x - a0.x, ja.y - a0.y);
    __half2 jl1 = __floats2half2_rn(ja.z - a1.x, ja.w - a1.y);
    __half2 jl2 = __floats2half2_rn(jb.x - a2.x, jb.y - a2.y);
    __half2 jl3 = __floats2half2_rn(jb.z - a3.x, jb.w - a3.y);
    ((uint4*)g_JHi)[b] = make_uint4(u32h2(jh0), u32h2(jh1), u32h2(jh2), u32h2(jh3));
    ((uint4*)g_JLo)[b] = make_uint4(u32h2(jl0), u32h2(jl1), u32h2(jl2), u32h2(jl3));
    float4 va = V4[f], vb = V4[f + 1];
    ((uint4*)g_VH)[b] = make_uint4(
        u32h2(__floats2half2_rn(va.x, va.y)), u32h2(__floats2half2_rn(va.z, va.w)),
        u32h2(__floats2half2_rn(vb.x, vb.y)), u32h2(__floats2half2_rn(vb.z, vb.w)));
    float4 ka = K4[f], kb = K4[f + 1];
    ka.x *= LOG2E; ka.y *= LOG2E; ka.z *= LOG2E; ka.w *= LOG2E;
    kb.x *= LOG2E; kb.y *= LOG2E; kb.z *= LOG2E; kb.w *= LOG2E;
    __half2 kh0 = __floats2half2_rn(ka.x, ka.y), kh1 = __floats2half2_rn(ka.z, ka.w);
    __half2 kh2 = __floats2half2_rn(kb.x, kb.y), kh3 = __floats2half2_rn(kb.z, kb.w);
    float2 c0 = __half22float2(kh0), c1 = __half22float2(kh1);
    float2 c2 = __half22float2(kh2), c3 = __half22float2(kh3);
    __half2 kl0 = __floats2half2_rn(ka.x - c0.x, ka.y - c0.y);
    __half2 kl1 = __floats2half2_rn(ka.z - c1.x, ka.w - c1.y);
    __half2 kl2 = __floats2half2_rn(kb.x - c2.x, kb.y - c2.y);
    __half2 kl3 = __floats2half2_rn(kb.z - c3.x, kb.w - c3.y);
    ((uint4*)g_KHi)[b] = make_uint4(u32h2(kh0), u32h2(kh1), u32h2(kh2), u32h2(kh3));
    ((uint4*)g_KLo)[b] = make_uint4(u32h2(kl0), u32h2(kl1), u32h2(kl2), u32h2(kl3));
}

// ---- main kernel ----
__global__ __launch_bounds__(NTHREADS, 2)
void attn_mma_kernel(float* __restrict__ Og) {
    extern __shared__ char smem[];
    const uint32_t smb = smem_u32(smem);
    float* lred  = (float*)(smem + LRED);   // [0..127] partials, [128..159] 1/l
    float* msm   = lred + 160;              // [4][32]
    float* ostage = (float*)(smem + OSTAGE);

    const int tid  = threadIdx.x;
    const int lane = tid & 31;
    const int wid  = tid >> 5;
    const int wm   = wid & 1;           // m-strip: rows 16*wm..+15 (of 32)
    const int wn   = wid >> 1;          // j-quarter 0..3
    const int m0   = wm * 16;
    const int j0   = wn * 16;
    const unsigned pbo   = (unsigned)blockIdx.y * 65536u;
    const unsigned kbase = (unsigned)blockIdx.x * 32u;

    // J/V copy addressing (2 chunks/thread, c-row + 16B j-chunk)
    uint32_t dstoff[2];
    unsigned srcoff[2];
    #pragma unroll
    for (int t = 0; t < 2; t++) {
        int flat = tid + t * NTHREADS;
        uint32_t c = (uint32_t)(flat >> 3), ch = (uint32_t)(flat & 7);
        dstoff[t] = c * 128u + ((ch * 16u) ^ ((c & 7u) << 4));
        srcoff[t] = pbo + c * 1024u + ch * 8u;
    }

    // ---------- prologue: K tile (32 k, [c][k] layout) + stages 0,1 ----------
    {
        uint32_t c = (uint32_t)(tid >> 2), ch = (uint32_t)(tid & 3);
        uint32_t dst = c * 128u + ((ch * 16u) ^ ((c & 7u) << 4));
        unsigned so = pbo + c * 1024u + kbase + ch * 8u;
        cpa16(smb + KHIo + dst, g_KHi + so);
        cpa16(smb + KLOo + dst, g_KLo + so);
    }
    #pragma unroll
    for (int t = 0; t < 2; t++) {
        cpa16(smb + STG + JHIo + dstoff[t], g_JHi + srcoff[t]);
        cpa16(smb + STG + JLOo + dstoff[t], g_JLo + srcoff[t]);
        cpa16(smb + STG + VHo  + dstoff[t], g_VH  + srcoff[t]);
    }
    CP_COMMIT();
    #pragma unroll
    for (int t = 0; t < 2; t++) {
        cpa16(smb + STG + SSZ + JHIo + dstoff[t], g_JHi + srcoff[t] + 64u);
        cpa16(smb + STG + SSZ + JLOo + dstoff[t], g_JLo + srcoff[t] + 64u);
        cpa16(smb + STG + SSZ + VHo  + dstoff[t], g_VH  + srcoff[t] + 64u);
    }
    CP_COMMIT();
    CP_WAIT1();
    __syncthreads();

    // lane-constant address pieces
    const uint32_t xorl  = (uint32_t)(lane & 7) << 4;
    const uint32_t bRowJ = (uint32_t)((lane & 15)) * 128u;
    const uint32_t bColJ = (uint32_t)((lane >> 4) << 4);
    const uint32_t bcol  = ((uint32_t)(j0 * 2) + bColJ) ^ xorl;
    const uint32_t vRow16 = (uint32_t)(lane & 15) * 128u;
    const uint32_t vcol16 = ((uint32_t)(j0 * 2) + ((uint32_t)(lane >> 4) << 4)) ^ xorl;
    // A-frag trans-load: c-row (lane&7)+((lane>>4)<<3), k-bytes m0*2 + ((lane>>3)&1)*16
    const uint32_t aRowT = ((uint32_t)((lane & 7) + ((lane >> 4) << 3))) * 128u;
    const uint32_t aColT = (((uint32_t)(m0 * 2)) + ((((uint32_t)lane >> 3) & 1u) << 4)) ^ xorl;

    // ---------- cache K fragments ----------
    uint32_t kfh[4][4], kfl[4][4];
    #pragma unroll
    for (int ks = 0; ks < 4; ks++) {
        uint32_t base = (uint32_t)(ks * 16) * 128u + aRowT + aColT;
        ldsm4t(kfh[ks], smb + KHIo + base);
        ldsm4t(kfl[ks], smb + KLOo + base);
    }

    float D2[8][4];
    #pragma unroll
    for (int nt = 0; nt < 8; nt++)
        #pragma unroll
        for (int i = 0; i < 4; i++) D2[nt][i] = 0.0f;
    float rsum[2] = {0.0f, 0.0f};
    float mrow0 = -1e30f, mrow1 = -1e30f;

    uint32_t curst = 0;

    for (int jt = 0; jt < 16; jt++) {
        const uint32_t cur = STG + curst * SSZ;

        if (jt < 14) {
            uint32_t ns = curst + 2u; if (ns >= 3u) ns -= 3u;
            const uint32_t nxt = STG + ns * SSZ;
            unsigned go = (unsigned)(jt + 2) * 64u;
            #pragma unroll
            for (int t = 0; t < 2; t++) {
                cpa16(smb + nxt + JHIo + dstoff[t], g_JHi + srcoff[t] + go);
                cpa16(smb + nxt + JLOo + dstoff[t], g_JLo + srcoff[t] + go);
                cpa16(smb + nxt + VHo  + dstoff[t], g_VH  + srcoff[t] + go);
            }
            CP_COMMIT();
        }

        // ---------- GEMM1: S̃[16 x 16] fp16 3-pass ----------
        float S[2][4];
        #pragma unroll
        for (int nt = 0; nt < 2; nt++)
            #pragma unroll
            for (int i = 0; i < 4; i++) S[nt][i] = 0.0f;

        #pragma unroll
        for (int ks = 0; ks < 4; ks++) {
            uint32_t jrow = (uint32_t)(ks * 16) * 128u + bRowJ;
            uint32_t bh[4], bl[4];
            ldsm4t(bh, smb + cur + JHIo + jrow + bcol);
            ldsm4t(bl, smb + cur + JLOo + jrow + bcol);
            #pragma unroll
            for (int q = 0; q < 2; q++) {
                mma_f16(S[q], kfh[ks], bh[2 * q], bh[2 * q + 1]);
                mma_f16(S[q], kfh[ks], bl[2 * q], bl[2 * q + 1]);
                mma_f16(S[q], kfl[ks], bh[2 * q], bh[2 * q + 1]);
            }
        }

        // ---------- online softmax (log2 domain) ----------
        float mx0 = fmaxf(fmaxf(S[0][0], S[0][1]), fmaxf(S[1][0], S[1][1]));
        float mx1 = fmaxf(fmaxf(S[0][2], S[0][3]), fmaxf(S[1][2], S[1][3]));
        mx0 = fmaxf(mx0, __shfl_xor_sync(0xffffffffu, mx0, 1));
        mx0 = fmaxf(mx0, __shfl_xor_sync(0xffffffffu, mx0, 2));
        mx1 = fmaxf(mx1, __shfl_xor_sync(0xffffffffu, mx1, 1));
        mx1 = fmaxf(mx1, __shfl_xor_sync(0xffffffffu, mx1, 2));
        bool changed = (mx0 > mrow0) || (mx1 > mrow1);
        if (__any_sync(0xffffffffu, changed)) {
            float nm0 = fmaxf(mrow0, mx0), nm1 = fmaxf(mrow1, mx1);
            float a0 = ex2f(mrow0 - nm0), a1 = ex2f(mrow1 - nm1);
            mrow0 = nm0; mrow1 = nm1;
            rsum[0] *= a0; rsum[1] *= a1;
            #pragma unroll
            for (int nt = 0; nt < 8; nt++) {
                D2[nt][0] *= a0; D2[nt][1] *= a0;
                D2[nt][2] *= a1; D2[nt][3] *= a1;
            }
        }

        uint32_t phi[4];
        #pragma unroll
        for (int q = 0; q < 2; q++) {
            const float* s = S[q];
            float p0 = ex2f(s[0] - mrow0), p1 = ex2f(s[1] - mrow0);
            float p2 = ex2f(s[2] - mrow1), p3 = ex2f(s[3] - mrow1);
            rsum[0] += p0 + p1;
            rsum[1] += p2 + p3;
            phi[q * 2]     = u32h2(__floats2half2_rn(p0, p1));   // rows g,   k j0+q*8
            phi[q * 2 + 1] = u32h2(__floats2half2_rn(p2, p3));   // rows g+8, k j0+q*8
        }
        // reorder to a-frag {a0:(g,k0),a1:(g+8,k0),a2:(g,k8),a3:(g+8,k8)} == phi as laid out ✓

        // ---------- GEMM2: D2 += P x V^T (k=16), 4 ldsm + 8 mma ----------
        #pragma unroll
        for (int ntp = 0; ntp < 4; ntp++) {
            uint32_t vh[4];
            uint32_t vr = (uint32_t)(ntp * 16) * 128u + vRow16;
            ldsm4(vh, smb + cur + VHo + vr + vcol16);
            mma_f16(D2[2 * ntp],     phi, vh[0], vh[2]);
            mma_f16(D2[2 * ntp + 1], phi, vh[1], vh[3]);
        }

        if (jt < 14) { CP_WAIT1(); }
        else if (jt == 14) { CP_WAIT0(); }
        __syncthreads();
        curst = (curst == 2u) ? 0u : curst + 1u;
    }

    // ---------- Epilogue: reconcile maxes across the 4 j-quarter groups ----------
    const int r = m0 + (lane >> 2);   // 0..31
    if ((lane & 3) == 0) {
        msm[wn * 32 + r]     = mrow0;
        msm[wn * 32 + r + 8] = mrow1;
    }
    __syncthreads();
    {
        float M0 = fmaxf(fmaxf(msm[r], msm[32 + r]), fmaxf(msm[64 + r], msm[96 + r]));
        float M1 = fmaxf(fmaxf(msm[r + 8], msm[32 + r + 8]), fmaxf(msm[64 + r + 8], msm[96 + r + 8]));
        float s0 = ex2f(mrow0 - M0), s1 = ex2f(mrow1 - M1);
        rsum[0] *= s0; rsum[1] *= s1;
        #pragma unroll
        for (int nt = 0; nt < 8; nt++) {
            D2[nt][0] *= s0; D2[nt][1] *= s0;
            D2[nt][2] *= s1; D2[nt][3] *= s1;
        }
    }

    #pragma unroll
    for (int rr = 0; rr < 2; rr++) {
        float v = rsum[rr];
        v += __shfl_xor_sync(0xffffffffu, v, 1);
        v += __shfl_xor_sync(0xffffffffu, v, 2);
        if ((lane & 3) == 0)
            lred[wn * 32 + m0 + rr * 8 + (lane >> 2)] = v;
    }
    __syncthreads();
    if (tid < 32)
        lred[128 + tid] = 1.0f / (lred[tid] + lred[32 + tid] + lred[64 + tid] + lred[96 + tid]);

    // accumulate the 4 j-quarter partial outputs into ostage
    #pragma unroll
    for (int g = 0; g < 4; g++) {
        if (wn == g) {
            #pragma unroll
            for (int nt = 0; nt < 8; nt++) {
                int c0 = nt * 8 + 2 * (lane & 3);
                int rw = m0 + (lane >> 2);
                if (g == 0) {
                    ostage[c0 * 32 + rw]           = D2[nt][0];
                    ostage[(c0 + 1) * 32 + rw]     = D2[nt][1];
                    ostage[c0 * 32 + rw + 8]       = D2[nt][2];
                    ostage[(c0 + 1) * 32 + rw + 8] = D2[nt][3];
                } else {
                    ostage[c0 * 32 + rw]           += D2[nt][0];
                    ostage[(c0 + 1) * 32 + rw]     += D2[nt][1];
                    ostage[c0 * 32 + rw + 8]       += D2[nt][2];
                    ostage[(c0 + 1) * 32 + rw + 8] += D2[nt][3];
                }
            }
        }
        __syncthreads();
    }

    // final write: out[c][kbase + k] * (1/l[k])
    #pragma unroll
    for (int t = 0; t < 2; t++) {
        int flat = tid + t * NTHREADS;   // 512 float4
        int c = flat >> 3, k4 = flat & 7;
        float4 v  = *(float4*)(ostage + c * 32 + k4 * 4);
        float4 iv = *(float4*)(lred + 128 + k4 * 4);
        v.x *= iv.x; v.y *= iv.y; v.z *= iv.z; v.w *= iv.w;
        *(float4*)(Og + pbo + (unsigned)c * 1024u + kbase + (unsigned)k4 * 4u) = v;
    }
}

extern "C" void kernel_launch(void* const* d_in, const int* in_sizes, int n_in,
                              void* d_out, int out_size) {
    const float* Kg = (const float*)d_in[0];
    const float* Jg = (const float*)d_in[1];
    const float* Vg = (const float*)d_in[2];
    float* Og = (float*)d_out;

    prep_kernel<<<2048, 256>>>((const float4*)Kg, (const float4*)Jg, (const float4*)Vg);

    cudaFuncSetAttribute(attn_mma_kernel,
                         cudaFuncAttributeMaxDynamicSharedMemorySize, SMEM_BYTES);
    dim3 grid(32, 64);   // 32 k-tiles x 64 batches = 2048 CTAs
    attn_mma_kernel<<<grid, NTHREADS, SMEM_BYTES>>>(Og);
}

// round 17
// speedup vs baseline: 1.2892x; 1.2892x over previous
#include <cuda_runtime.h>
#include <cuda_fp16.h>
#include <cuda_bf16.h>
#include <cstdint>

// self_attention_9225589752302 — round 16: R14 main kernel + in-kernel K split
// (K read f32 once per CTA, log2e+hi/lo split in regs, swizzled STS, ldsm4t frags).
// Prep = J/V only. GEMM1 fp16 3-pass (log2 domain), GEMM2 fp16 1-pass, 3-stage cp.async.
// grid (16 k-tiles, 64 batches), 256 thr, 2 CTAs/SM.

#define NTHREADS 256
#define LOG2E 1.4426950408889634f

// ---- global scratch (J/V only) ----
__device__ __half g_JHi[4194304];   // [pb][c=64][j=1024]
__device__ __half g_JLo[4194304];
__device__ __half g_VH [4194304];   // [pb][c=64][j=1024] single fp16

// ---- smem: K 16KB | 3 stages x 24KB | LRED ----
#define KHIo 0u            // K [c=64 rows][128B of k] fp16, swz ((c&7)<<4)
#define KLOo 8192u
#define STG  16384u
#define SSZ  24576u
#define JHIo 0u
#define JLOo 8192u
#define VHo  16384u
#define LRED (16384u + 3u * 24576u)     // 90112
#define SMEM_BYTES (LRED + 1536u)
#define OSTAGE 0u

static __device__ __forceinline__ uint32_t smem_u32(const void* p) {
    uint32_t a;
    asm("{ .reg .u64 t; cvta.to.shared.u64 t, %1; cvt.u32.u64 %0, t; }" : "=r"(a) : "l"(p));
    return a;
}
static __device__ __forceinline__ float ex2f(float x) {
    float r;
    asm("ex2.approx.ftz.f32 %0, %1;" : "=f"(r) : "f"(x));
    return r;
}
static __device__ __forceinline__ void cpa16(uint32_t dst, const void* src) {
    asm volatile("cp.async.cg.shared.global [%0], [%1], 16;" :: "r"(dst), "l"(src));
}
#define CP_COMMIT() asm volatile("cp.async.commit_group;" ::: "memory")
#define CP_WAIT1()  asm volatile("cp.async.wait_group 1;" ::: "memory")
#define CP_WAIT0()  asm volatile("cp.async.wait_group 0;" ::: "memory")

static __device__ __forceinline__ void ldsm4t(uint32_t r[4], uint32_t a) {
    asm volatile("ldmatrix.sync.aligned.m8n8.x4.trans.shared.b16 {%0,%1,%2,%3}, [%4];"
        : "=r"(r[0]), "=r"(r[1]), "=r"(r[2]), "=r"(r[3]) : "r"(a));
}
static __device__ __forceinline__ void ldsm4(uint32_t r[4], uint32_t a) {
    asm volatile("ldmatrix.sync.aligned.m8n8.x4.shared.b16 {%0,%1,%2,%3}, [%4];"
        : "=r"(r[0]), "=r"(r[1]), "=r"(r[2]), "=r"(r[3]) : "r"(a));
}
static __device__ __forceinline__ void mma_f16(float d[4], const uint32_t a[4], uint32_t b0, uint32_t b1) {
    asm("mma.sync.aligned.m16n8k16.row.col.f32.f16.f16.f32 "
        "{%0,%1,%2,%3}, {%4,%5,%6,%7}, {%8,%9}, {%0,%1,%2,%3};"
        : "+f"(d[0]), "+f"(d[1]), "+f"(d[2]), "+f"(d[3])
        : "r"(a[0]), "r"(a[1]), "r"(a[2]), "r"(a[3]), "r"(b0), "r"(b1));
}
static __device__ __forceinline__ uint32_t u32h2(__half2 h) { return *(uint32_t*)&h; }

// ---- prep: J hi/lo + V fp16 only (pure elementwise) ----
__global__ __launch_bounds__(256)
void prep_kernel(const float4* __restrict__ J4, const float4* __restrict__ V4) {
    unsigned b = blockIdx.x * 256u + threadIdx.x;   // uint4 output index
    unsigned f = b * 2u;
    float4 ja = J4[f], jb = J4[f + 1];
    __half2 jh0 = __floats2half2_rn(ja.x, ja.y), jh1 = __floats2half2_rn(ja.z, ja.w);
    __half2 jh2 = __floats2half2_rn(jb.x, jb.y), jh3 = __floats2half2_rn(jb.z, jb.w);
    float2 a0 = __half22float2(jh0), a1 = __half22float2(jh1);
    float2 a2 = __half22float2(jh2), a3 = __half22float2(jh3);
    __half2 jl0 = __floats2half2_rn(ja.x - a0.x, ja.y - a0.y);
    __half2 jl1 = __floats2half2_rn(ja.z - a1.x, ja.w - a1.y);
    __half2 jl2 = __floats2half2_rn(jb.x - a2.x, jb.y - a2.y);
    __half2 jl3 = __floats2half2_rn(jb.z - a3.x, jb.w - a3.y);
    ((uint4*)g_JHi)[b] = make_uint4(u32h2(jh0), u32h2(jh1), u32h2(jh2), u32h2(jh3));
    ((uint4*)g_JLo)[b] = make_uint4(u32h2(jl0), u32h2(jl1), u32h2(jl2), u32h2(jl3));
    float4 va = V4[f], vb = V4[f + 1];
    ((uint4*)g_VH)[b] = make_uint4(
        u32h2(__floats2half2_rn(va.x, va.y)), u32h2(__floats2half2_rn(va.z, va.w)),
        u32h2(__floats2half2_rn(vb.x, vb.y)), u32h2(__floats2half2_rn(vb.z, vb.w)));
}

// ---- main kernel ----
__global__ __launch_bounds__(NTHREADS, 2)
void attn_mma_kernel(const float* __restrict__ Kg, float* __restrict__ Og) {
    extern __shared__ char smem[];
    const uint32_t smb = smem_u32(smem);
    float* lred  = (float*)(smem + LRED);
    float* msm   = lred + 192;
    float* ostage = (float*)(smem + OSTAGE);

    const int tid  = threadIdx.x;
    const int lane = tid & 31;
    const int wid  = tid >> 5;
    const int wm   = wid & 3;
    const int wn   = wid >> 2;
    const int m0   = wm * 16;
    const int j0   = wn * 32;
    const unsigned pbo   = (unsigned)blockIdx.y * 65536u;
    const unsigned kbase = (unsigned)blockIdx.x * 64u;

    // J/V copy addressing: 2 chunks per thread (c-row, 16B j-chunk)
    uint32_t dstoff[2];
    unsigned srcoff[2];
    #pragma unroll
    for (int t = 0; t < 2; t++) {
        int flat = tid + t * NTHREADS;
        uint32_t c = (uint32_t)(flat >> 3), ch = (uint32_t)(flat & 7);
        dstoff[t] = c * 128u + ((ch * 16u) ^ ((c & 7u) << 4));
        srcoff[t] = pbo + c * 1024u + ch * 8u;
    }

    // ---------- prologue: issue stage 0,1 cp.async first (in flight under K work) ----------
    #pragma unroll
    for (int t = 0; t < 2; t++) {
        cpa16(smb + STG + JHIo + dstoff[t], g_JHi + srcoff[t]);
        cpa16(smb + STG + JLOo + dstoff[t], g_JLo + srcoff[t]);
        cpa16(smb + STG + VHo  + dstoff[t], g_VH  + srcoff[t]);
    }
    CP_COMMIT();
    #pragma unroll
    for (int t = 0; t < 2; t++) {
        cpa16(smb + STG + SSZ + JHIo + dstoff[t], g_JHi + srcoff[t] + 64u);
        cpa16(smb + STG + SSZ + JLOo + dstoff[t], g_JLo + srcoff[t] + 64u);
        cpa16(smb + STG + SSZ + VHo  + dstoff[t], g_VH  + srcoff[t] + 64u);
    }
    CP_COMMIT();

    // ---------- K tile: f32 LDG (once, CTA-exclusive) -> log2e + hi/lo split -> STS ----------
    #pragma unroll
    for (int t = 0; t < 2; t++) {
        int flat = tid + t * NTHREADS;             // 512 16B-chunks (64 rows x 8)
        uint32_t c = (uint32_t)(flat >> 3), ch = (uint32_t)(flat & 7);
        const float* src = Kg + pbo + c * 1024u + kbase + ch * 8u;
        float4 ka = *(const float4*)src;
        float4 kb = *(const float4*)(src + 4);
        ka.x *= LOG2E; ka.y *= LOG2E; ka.z *= LOG2E; ka.w *= LOG2E;
        kb.x *= LOG2E; kb.y *= LOG2E; kb.z *= LOG2E; kb.w *= LOG2E;
        __half2 h0 = __floats2half2_rn(ka.x, ka.y), h1 = __floats2half2_rn(ka.z, ka.w);
        __half2 h2 = __floats2half2_rn(kb.x, kb.y), h3 = __floats2half2_rn(kb.z, kb.w);
        float2 c0 = __half22float2(h0), c1 = __half22float2(h1);
        float2 c2 = __half22float2(h2), c3 = __half22float2(h3);
        __half2 l0 = __floats2half2_rn(ka.x - c0.x, ka.y - c0.y);
        __half2 l1 = __floats2half2_rn(ka.z - c1.x, ka.w - c1.y);
        __half2 l2 = __floats2half2_rn(kb.x - c2.x, kb.y - c2.y);
        __half2 l3 = __floats2half2_rn(kb.z - c3.x, kb.w - c3.y);
        uint32_t dst = c * 128u + ((ch * 16u) ^ ((c & 7u) << 4));
        *(uint4*)(smem + KHIo + dst) = make_uint4(u32h2(h0), u32h2(h1), u32h2(h2), u32h2(h3));
        *(uint4*)(smem + KLOo + dst) = make_uint4(u32h2(l0), u32h2(l1), u32h2(l2), u32h2(l3));
    }
    CP_WAIT1();   // stage 0 complete
    __syncthreads();

    // lane-constant address pieces
    const uint32_t xorl  = (uint32_t)(lane & 7) << 4;
    const uint32_t bRowJ = (uint32_t)((lane & 15)) * 128u;
    const uint32_t bColJ = (uint32_t)((lane >> 4) << 4);
    const uint32_t vRow  = (uint32_t)(lane & 7) * 128u;
    const uint32_t vColH = (uint32_t)((lane >> 3) << 4);
    const uint32_t vcol  = ((uint32_t)(j0 * 2) + vColH) ^ xorl;
    // A-frag trans-load: c-row (lane&7)+((lane>>4)<<3), k-bytes m0*2 + ((lane>>3)&1)*16
    const uint32_t aRowT = ((uint32_t)((lane & 7) + ((lane >> 4) << 3))) * 128u;
    const uint32_t aColT = (((uint32_t)(m0 * 2)) + ((((uint32_t)lane >> 3) & 1u) << 4)) ^ xorl;

    // ---------- cache K fragments (ldsm trans) ----------
    uint32_t kfh[4][4], kfl[4][4];
    #pragma unroll
    for (int ks = 0; ks < 4; ks++) {
        uint32_t base = (uint32_t)(ks * 16) * 128u + aRowT + aColT;
        ldsm4t(kfh[ks], smb + KHIo + base);
        ldsm4t(kfl[ks], smb + KLOo + base);
    }

    float D2[8][4];
    #pragma unroll
    for (int nt = 0; nt < 8; nt++)
        #pragma unroll
        for (int i = 0; i < 4; i++) D2[nt][i] = 0.0f;
    float rsum[2] = {0.0f, 0.0f};
    float mrow0 = -1e30f, mrow1 = -1e30f;

    uint32_t curst = 0;

    for (int jt = 0; jt < 16; jt++) {
        const uint32_t cur = STG + curst * SSZ;

        if (jt < 14) {
            uint32_t ns = curst + 2u; if (ns >= 3u) ns -= 3u;
            const uint32_t nxt = STG + ns * SSZ;
            unsigned go = (unsigned)(jt + 2) * 64u;
            #pragma unroll
            for (int t = 0; t < 2; t++) {
                cpa16(smb + nxt + JHIo + dstoff[t], g_JHi + srcoff[t] + go);
                cpa16(smb + nxt + JLOo + dstoff[t], g_JLo + srcoff[t] + go);
                cpa16(smb + nxt + VHo  + dstoff[t], g_VH  + srcoff[t] + go);
            }
            CP_COMMIT();
        }

        // ---------- GEMM1: S̃[16 x 32] (log2 domain) fp16 3-pass ----------
        float S[4][4];
        #pragma unroll
        for (int nt = 0; nt < 4; nt++)
            #pragma unroll
            for (int i = 0; i < 4; i++) S[nt][i] = 0.0f;

        #pragma unroll
        for (int ks = 0; ks < 4; ks++) {
            uint32_t jrow = (uint32_t)(ks * 16) * 128u + bRowJ;
            #pragma unroll
            for (int ntp = 0; ntp < 2; ntp++) {
                uint32_t bh[4], bl[4];
                uint32_t bcol = ((uint32_t)((j0 + ntp * 16) * 2) + bColJ) ^ xorl;
                ldsm4t(bh, smb + cur + JHIo + jrow + bcol);
                ldsm4t(bl, smb + cur + JLOo + jrow + bcol);
                #pragma unroll
                for (int q = 0; q < 2; q++) {
                    int nt = 2 * ntp + q;
                    mma_f16(S[nt], kfh[ks], bh[2 * q], bh[2 * q + 1]);
                    mma_f16(S[nt], kfh[ks], bl[2 * q], bl[2 * q + 1]);
                    mma_f16(S[nt], kfl[ks], bh[2 * q], bh[2 * q + 1]);
                }
            }
        }

        // ---------- online softmax (log2 domain) ----------
        float mx0 = -1e30f, mx1 = -1e30f;
        #pragma unroll
        for (int nt = 0; nt < 4; nt++) {
            mx0 = fmaxf(mx0, fmaxf(S[nt][0], S[nt][1]));
            mx1 = fmaxf(mx1, fmaxf(S[nt][2], S[nt][3]));
        }
        mx0 = fmaxf(mx0, __shfl_xor_sync(0xffffffffu, mx0, 1));
        mx0 = fmaxf(mx0, __shfl_xor_sync(0xffffffffu, mx0, 2));
        mx1 = fmaxf(mx1, __shfl_xor_sync(0xffffffffu, mx1, 1));
        mx1 = fmaxf(mx1, __shfl_xor_sync(0xffffffffu, mx1, 2));
        bool changed = (mx0 > mrow0) || (mx1 > mrow1);
        if (__any_sync(0xffffffffu, changed)) {
            float nm0 = fmaxf(mrow0, mx0), nm1 = fmaxf(mrow1, mx1);
            float a0 = ex2f(mrow0 - nm0), a1 = ex2f(mrow1 - nm1);
            mrow0 = nm0; mrow1 = nm1;
            rsum[0] *= a0; rsum[1] *= a1;
            #pragma unroll
            for (int nt = 0; nt < 8; nt++) {
                D2[nt][0] *= a0; D2[nt][1] *= a0;
                D2[nt][2] *= a1; D2[nt][3] *= a1;
            }
        }

        uint32_t phi[2][4];
        #pragma unroll
        for (int g = 0; g < 2; g++)
            #pragma unroll
            for (int q = 0; q < 2; q++) {
                const float* s = S[2 * g + q];
                float p0 = ex2f(s[0] - mrow0), p1 = ex2f(s[1] - mrow0);
                float p2 = ex2f(s[2] - mrow1), p3 = ex2f(s[3] - mrow1);
                rsum[0] += p0 + p1;
                rsum[1] += p2 + p3;
                phi[g][2 * q]     = u32h2(__floats2half2_rn(p0, p1));
                phi[g][2 * q + 1] = u32h2(__floats2half2_rn(p2, p3));
            }

        // ---------- GEMM2: D2 += P x V^T, fp16 1-pass ----------
        #pragma unroll
        for (int nt = 0; nt < 8; nt++) {
            uint32_t vh[4];
            uint32_t vr = (uint32_t)(nt * 8) * 128u + vRow;
            ldsm4(vh, smb + cur + VHo + vr + vcol);
            #pragma unroll
            for (int g = 0; g < 2; g++)
                mma_f16(D2[nt], phi[g], vh[2 * g], vh[2 * g + 1]);
        }

        if (jt < 14) { CP_WAIT1(); }
        else if (jt == 14) { CP_WAIT0(); }
        __syncthreads();
        curst = (curst == 2u) ? 0u : curst + 1u;
    }

    // ---------- Epilogue: reconcile maxes across the two j-half warps ----------
    const int r = m0 + (lane >> 2);
    if ((lane & 3) == 0) {
        msm[wn * 64 + r]     = mrow0;
        msm[wn * 64 + r + 8] = mrow1;
    }
    __syncthreads();
    {
        float M0 = fmaxf(msm[r], msm[64 + r]);
        float M1 = fmaxf(msm[r + 8], msm[64 + r + 8]);
        float s0 = ex2f(mrow0 - M0), s1 = ex2f(mrow1 - M1);
        rsum[0] *= s0; rsum[1] *= s1;
        #pragma unroll
        for (int nt = 0; nt < 8; nt++) {
            D2[nt][0] *= s0; D2[nt][1] *= s0;
            D2[nt][2] *= s1; D2[nt][3] *= s1;
        }
    }

    #pragma unroll
    for (int rr = 0; rr < 2; rr++) {
        float v = rsum[rr];
        v += __shfl_xor_sync(0xffffffffu, v, 1);
        v += __shfl_xor_sync(0xffffffffu, v, 2);
        if ((lane & 3) == 0)
            lred[wn * 64 + m0 + rr * 8 + (lane >> 2)] = v;
    }
    __syncthreads();
    if (tid < 64) lred[128 + tid] = 1.0f / (lred[tid] + lred[64 + tid]);

    if (wn == 0) {
        #pragma unroll
        for (int nt = 0; nt < 8; nt++) {
            int c0 = nt * 8 + 2 * (lane & 3);
            int rw = m0 + (lane >> 2);
            ostage[c0 * 64 + rw]           = D2[nt][0];
            ostage[(c0 + 1) * 64 + rw]     = D2[nt][1];
            ostage[c0 * 64 + rw + 8]       = D2[nt][2];
            ostage[(c0 + 1) * 64 + rw + 8] = D2[nt][3];
        }
    }
    __syncthreads();
    if (wn == 1) {
        #pragma unroll
        for (int nt = 0; nt < 8; nt++) {
            int c0 = nt * 8 + 2 * (lane & 3);
            int rw = m0 + (lane >> 2);
            ostage[c0 * 64 + rw]           += D2[nt][0];
            ostage[(c0 + 1) * 64 + rw]     += D2[nt][1];
            ostage[c0 * 64 + rw + 8]       += D2[nt][2];
            ostage[(c0 + 1) * 64 + rw + 8] += D2[nt][3];
        }
    }
    __syncthreads();

    #pragma unroll
    for (int t = 0; t < 4; t++) {
        int flat = tid + t * NTHREADS;
        int c = flat >> 4, k4 = flat & 15;
        float4 v  = *(float4*)(ostage + c * 64 + k4 * 4);
        float4 iv = *(float4*)(lred + 128 + k4 * 4);
        v.x *= iv.x; v.y *= iv.y; v.z *= iv.z; v.w *= iv.w;
        *(float4*)(Og + pbo + (unsigned)c * 1024u + kbase + (unsigned)k4 * 4u) = v;
    }
}

extern "C" void kernel_launch(void* const* d_in, const int* in_sizes, int n_in,
                              void* d_out, int out_size) {
    const float* Kg = (const float*)d_in[0];
    const float* Jg = (const float*)d_in[1];
    const float* Vg = (const float*)d_in[2];
    float* Og = (float*)d_out;

    prep_kernel<<<2048, 256>>>((const float4*)Jg, (const float4*)Vg);

    cudaFuncSetAttribute(attn_mma_kernel,
                         cudaFuncAttributeMaxDynamicSharedMemorySize, SMEM_BYTES);
    dim3 grid(16, 64);
    attn_mma_kernel<<<grid, NTHREADS, SMEM_BYTES>>>(Kg, Og);
}